// round 17
// baseline (speedup 1.0000x reference)
#include <cuda_runtime.h>
#include <stdint.h>

#define CIN    64
#define COUT   64
#define HW     16384
#define NGRP   16

__device__ __forceinline__ int dp4a_us(unsigned a, int b, int c) {
    int r;
    asm("dp4a.u32.s32 %0, %1, %2, %3;" : "=r"(r) : "r"(a), "r"(b), "r"(c));
    return r;
}

__device__ __forceinline__ unsigned pack4(int a, int b, int c, int d) {
    unsigned lo = __byte_perm((unsigned)a, (unsigned)b, 0x0040);
    unsigned hi = __byte_perm((unsigned)c, (unsigned)d, 0x0040);
    return __byte_perm(lo, hi, 0x5410);
}

template<bool HASZP>
__device__ __forceinline__ void conv_body(const int* __restrict__ xb,
                                          float* __restrict__ ob,
                                          const int* s_w,
                                          const float4* s_P)
{
    // load 64 channels for ONE position: 32 coalesced LDG.32 (1 line each)
    unsigned xw[NGRP];
#pragma unroll
    for (int g = 0; g < NGRP; g++) {
        int v0 = __ldg(xb + (g * 4 + 0) * HW);
        int v1 = __ldg(xb + (g * 4 + 1) * HW);
        int v2 = __ldg(xb + (g * 4 + 2) * HW);
        int v3 = __ldg(xb + (g * 4 + 3) * HW);
        xw[g] = pack4(v0, v1, v2, v3);
    }

    // channel sum only needed when any wzp != 0
    float sxf = 0.0f;
    if (HASZP) {
        int sx = 0;
#pragma unroll
        for (int g = 0; g < NGRP; g++)
            sx = dp4a_us(xw[g], 0x01010101, sx);
        sxf = (float)sx;
    }

#pragma unroll
    for (int q = 0; q < NGRP; q++) {      // 16 output-channel quads
        int acc0 = 0, acc1 = 0, acc2 = 0, acc3 = 0;
#pragma unroll
        for (int g = 0; g < NGRP; g++) {
            int4 w4 = *(const int4*)(s_w + g * COUT + q * 4);
            acc0 = dp4a_us(xw[g], w4.x, acc0);
            acc1 = dp4a_us(xw[g], w4.y, acc1);
            acc2 = dp4a_us(xw[g], w4.z, acc2);
            acc3 = dp4a_us(xw[g], w4.w, acc3);
        }
        int accs[4] = {acc0, acc1, acc2, acc3};
#pragma unroll
        for (int j = 0; j < 4; j++) {
            const int o = q * 4 + j;
            float4 P = s_P[o];            // broadcast LDS.128: S, C0, C1
            float base = HASZP ? fmaf(P.z, sxf, P.y) : P.y;
            float f = fmaf(P.x, (float)accs[j], base);
            f = fminf(fmaxf(rintf(f), 0.0f), 255.0f);
            ob[o * HW] = f;               // coalesced STG.32
        }
    }
}

__global__ __launch_bounds__(256, 4) void conv_fused(
    const int*   __restrict__ x,
    float*       __restrict__ out,
    const int4*  __restrict__ w,
    const float* __restrict__ wscale,
    const int*   __restrict__ wzp,
    const float* __restrict__ bias,
    const float* __restrict__ iscale,
    const float* __restrict__ oscale,
    const int*   __restrict__ izp_p,
    const int*   __restrict__ ozp_p)
{
    __shared__ int    s_w[NGRP * COUT];   // [group][o] packed s8 weights
    __shared__ float4 s_P[COUT];          // (S, C0, C1, 0) per output channel

    const int tid = threadIdx.x;
    int myzp = 0;

    // ---- inlined prep: threads 0..63 each build one output channel ----
    if (tid < COUT) {
        const int o = tid;
        int sum = 0;
#pragma unroll
        for (int g = 0; g < NGRP; g++) {
            int4 v = __ldg(w + o * NGRP + g);
            sum += v.x + v.y + v.z + v.w;
            s_w[g * COUT + o] = (int)pack4(v.x, v.y, v.z, v.w);
        }
        myzp = __ldg(wzp + o);
        float s   = iscale[0] * wscale[o] / oscale[0];
        float izp = (float)izp_p[0];
        float zw  = (float)myzp;
        // round(f)+ozp == round(f+ozp) for integer ozp -> fold ozp into C0
        float C0  = bias[o] / oscale[0]
                  + s * izp * (64.0f * zw - (float)sum)
                  + (float)ozp_p[0];
        s_P[o] = make_float4(s, C0, -s * zw, 0.0f);
    }
    // barrier + block-wide OR of "any weight zero-point nonzero"
    const int haszp = __syncthreads_or(myzp != 0);

    const int gp = blockIdx.x * 256 + tid;   // one position per thread
    const int b  = gp >> 14;                  // / HW
    const int hw = gp & (HW - 1);

    const int* xb = x + b * (CIN * HW) + hw;
    float*     ob = out + b * (COUT * HW) + hw;

    if (haszp)
        conv_body<true>(xb, ob, s_w, s_P);
    else
        conv_body<false>(xb, ob, s_w, s_P);
}

extern "C" void kernel_launch(void* const* d_in, const int* in_sizes, int n_in,
                              void* d_out, int out_size) {
    // 0: x_quant (i32)  1: input_scale (f32)  2: input_zero_point (i32)
    // 3: weight_int8 (i32)  4: weight_scale (f32)  5: weight_zero_point (i32)
    // 6: bias_fp32 (f32)  7: output_scale (f32)  8: output_zero_point (i32)
    (void)in_sizes; (void)n_in; (void)out_size;

    // 524288 positions / 256 threads = 2048 blocks (exact)
    conv_fused<<<2048, 256>>>((const int*)d_in[0], (float*)d_out,
                              (const int4*)d_in[3], (const float*)d_in[4],
                              (const int*)d_in[5], (const float*)d_in[6],
                              (const float*)d_in[1], (const float*)d_in[7],
                              (const int*)d_in[2], (const int*)d_in[8]);
}